// round 5
// baseline (speedup 1.0000x reference)
#include <cuda_runtime.h>
#include <math.h>

#define NN 50000
#define NE 1250000
#define F  64
#define ED 7
#define NL 3
#define SCAN_BS 512
#define NSB ((NN + SCAN_BS - 1) / SCAN_BS)   // 98

// ---------------- scratch (static device memory; no allocs) ----------------
__device__ float g_feats[3][NN * F];   // feats[0..2]; layer-3 output lives only in uphead
__device__ float g_n1[NN * F];         // h @ w1[0:64]  (per-layer, reused)
__device__ float g_r[NN];              // h . att_r     (per-layer, reused)
__device__ float g_t[NN * F];          // normalized segment_sum(a * xj)
__device__ int   g_rowptr[NN + 1];
__device__ int   g_cursor[NN];
__device__ int   g_counts[NN];         // zero-initialized at load; re-zeroed in scan_a
__device__ int   g_bsums[NSB];
__device__ int    g_src[NE + 8];       // src node id, dst-sorted (+pad, pads stay 0)
__device__ float4 g_ea8[2 * NE + 16];  // edge_attr padded to 8 floats, dst-sorted

__device__ __forceinline__ float lrelu(float x) { return fmaxf(x, 0.01f * x); }

// ---------------- CSR build ----------------
__global__ void k_hist(const int* __restrict__ ei) {
    int e = blockIdx.x * blockDim.x + threadIdx.x;
    if (e < NE) atomicAdd(&g_counts[ei[NE + e]], 1);
}

__global__ void k_scan_a() {
    __shared__ int sh[SCAN_BS];
    int t = threadIdx.x;
    int i = blockIdx.x * SCAN_BS + t;
    int v = (i < NN) ? g_counts[i] : 0;
    if (i < NN) g_counts[i] = 0;                   // re-zero for next replay
    sh[t] = v;
    __syncthreads();
#pragma unroll
    for (int o = 1; o < SCAN_BS; o <<= 1) {
        int u = (t >= o) ? sh[t - o] : 0;
        __syncthreads();
        sh[t] += u;
        __syncthreads();
    }
    if (i < NN) g_rowptr[i] = sh[t] - v;           // exclusive within block
    if (t == SCAN_BS - 1) g_bsums[blockIdx.x] = sh[t];
}

__global__ void k_scan_b() {
    __shared__ int sh[128];
    int t = threadIdx.x;
    int v = (t < NSB) ? g_bsums[t] : 0;
    sh[t] = v;
    __syncthreads();
#pragma unroll
    for (int o = 1; o < 128; o <<= 1) {
        int u = (t >= o) ? sh[t - o] : 0;
        __syncthreads();
        sh[t] += u;
        __syncthreads();
    }
    if (t < NSB) g_bsums[t] = sh[t] - v;           // exclusive
}

__global__ void k_scan_c() {
    int i = blockIdx.x * SCAN_BS + threadIdx.x;
    if (i < NN) {
        int r = g_rowptr[i] + g_bsums[blockIdx.x];
        g_rowptr[i] = r;
        g_cursor[i] = r;
    }
    if (i == 0) g_rowptr[NN] = NE;
}

__global__ void k_scatter(const int* __restrict__ ei, const float* __restrict__ eattr) {
    int e = blockIdx.x * blockDim.x + threadIdx.x;
    if (e >= NE) return;
    int d = ei[NE + e];
    int pos = atomicAdd(&g_cursor[d], 1);
    g_src[pos] = ei[e];
    const float* ea = eattr + (long long)e * ED;
    g_ea8[2 * pos]     = make_float4(ea[0], ea[1], ea[2], ea[3]);
    g_ea8[2 * pos + 1] = make_float4(ea[4], ea[5], ea[6], 0.f);
}

// ---------------- fused gather + prep layer0 ----------------
__global__ void k_gprep(const int* __restrict__ x, const float* __restrict__ emb,
                        const float* __restrict__ w1, const float* __restrict__ ar) {
    __shared__ float s_w[F * F];
    __shared__ float s_ar[F];
    __shared__ float s_h[8][F];
    int tid = threadIdx.x;
    for (int i = tid; i < F * F; i += blockDim.x) s_w[i] = w1[i];
    if (tid < F) s_ar[tid] = ar[tid];
    __syncthreads();
    int warp = tid >> 5, lane = tid & 31;
    int node = blockIdx.x * 8 + warp;
    if (node >= NN) return;
    long long row = (long long)x[node] * F;
    float2 h2 = reinterpret_cast<const float2*>(emb + row)[lane];
    reinterpret_cast<float2*>(&s_h[warp][0])[lane] = h2;
    reinterpret_cast<float2*>(g_feats[0] + node * F)[lane] = h2;
    __syncwarp();
    float a0 = 0.f, a1 = 0.f;
#pragma unroll 16
    for (int k = 0; k < F; k++) {
        float hv = s_h[warp][k];
        float2 wv = reinterpret_cast<const float2*>(s_w + k * F)[lane];
        a0 += hv * wv.x;
        a1 += hv * wv.y;
    }
    reinterpret_cast<float2*>(g_n1 + node * F)[lane] = make_float2(a0, a1);
    float2 ar2 = reinterpret_cast<const float2*>(s_ar)[lane];
    float p = h2.x * ar2.x + h2.y * ar2.y;
#pragma unroll
    for (int o = 16; o; o >>= 1) p += __shfl_xor_sync(0xffffffffu, p, o);
    if (lane == 0) g_r[node] = p;
}

// ---------------- edge kernel: half-warp per edge, float4 features, 3-stage pipeline ----------------
__global__ void k_edge(const float* __restrict__ w1, const float* __restrict__ al) {
    int tid = threadIdx.x;
    int warp = tid >> 5, lane = tid & 31;
    int node = blockIdx.x * 8 + warp;
    if (node >= NN) return;
    int g  = lane >> 4;        // half-warp group: which edge of the pair
    int t  = lane & 15;        // sublane within group
    int fb = 4 * t;            // this lane owns features fb..fb+3

    const float* wb = w1 + F * F;  // rows 64..70 (edge_attr part of lin1)
    float4 W0 = *reinterpret_cast<const float4*>(wb + 0 * F + fb);
    float4 W1 = *reinterpret_cast<const float4*>(wb + 1 * F + fb);
    float4 W2 = *reinterpret_cast<const float4*>(wb + 2 * F + fb);
    float4 W3 = *reinterpret_cast<const float4*>(wb + 3 * F + fb);
    float4 W4 = *reinterpret_cast<const float4*>(wb + 4 * F + fb);
    float4 W5 = *reinterpret_cast<const float4*>(wb + 5 * F + fb);
    float4 W6 = *reinterpret_cast<const float4*>(wb + 6 * F + fb);
    float4 AL = *reinterpret_cast<const float4*>(al + fb);
    float ri = g_r[node];

    int beg = g_rowptr[node], end = g_rowptr[node + 1];
    float  s   = 0.f;
    float4 acc = make_float4(0.f, 0.f, 0.f, 0.f);

    // ---- pipeline prime (arrays padded; pad src = 0 is a valid node) ----
    int i0 = beg + g;
    int s0 = g_src[i0];            // src for pair 0 (this group's edge)
    int s1 = g_src[i0 + 2];        // src for pair 1
    float4 ea0 = g_ea8[2 * i0];
    float4 eb0 = g_ea8[2 * i0 + 1];
    float4 v0  = *reinterpret_cast<const float4*>(g_n1 + s0 * F + fb);

    int p = beg;
    for (; p + 2 <= end; p += 2) {
        float4 vC = v0, eaC = ea0, ebC = eb0;
        // prefetch: v for next pair uses s1 (resolved last iteration)
        v0 = *reinterpret_cast<const float4*>(g_n1 + s1 * F + fb);
        s0 = s1;
        s1 = g_src[p + 4 + g];                 // src two pairs ahead
        ea0 = g_ea8[2 * (p + 2 + g)];
        eb0 = g_ea8[2 * (p + 2 + g) + 1];
        // edge MLP contribution for 4 features
        float4 c;
        c.x = eaC.x * W0.x + eaC.y * W1.x + eaC.z * W2.x + eaC.w * W3.x
            + ebC.x * W4.x + ebC.y * W5.x + ebC.z * W6.x;
        c.y = eaC.x * W0.y + eaC.y * W1.y + eaC.z * W2.y + eaC.w * W3.y
            + ebC.x * W4.y + ebC.y * W5.y + ebC.z * W6.y;
        c.z = eaC.x * W0.z + eaC.y * W1.z + eaC.z * W2.z + eaC.w * W3.z
            + ebC.x * W4.z + ebC.y * W5.z + ebC.z * W6.z;
        c.w = eaC.x * W0.w + eaC.y * W1.w + eaC.z * W2.w + eaC.w * W3.w
            + ebC.x * W4.w + ebC.y * W5.w + ebC.z * W6.w;
        float4 xv;
        xv.x = lrelu(vC.x + c.x);
        xv.y = lrelu(vC.y + c.y);
        xv.z = lrelu(vC.z + c.z);
        xv.w = lrelu(vC.w + c.w);
        float part = xv.x * AL.x + xv.y * AL.y + xv.z * AL.z + xv.w * AL.w;
        // 16-lane butterfly: one chain reduces BOTH groups' edges
#pragma unroll
        for (int o = 8; o; o >>= 1) part += __shfl_xor_sync(0xffffffffu, part, o);
        float w = __expf(lrelu(part + ri));
        s += w;
        acc.x = fmaf(w, xv.x, acc.x);
        acc.y = fmaf(w, xv.y, acc.y);
        acc.z = fmaf(w, xv.z, acc.z);
        acc.w = fmaf(w, xv.w, acc.w);
    }
    // ---- remainder edge (odd degree): both groups compute it, only g==0 accumulates ----
    if ((end - beg) & 1) {
        int ir = end - 1;
        int srcR = g_src[ir];
        float4 ea = g_ea8[2 * ir], eb = g_ea8[2 * ir + 1];
        float4 v = *reinterpret_cast<const float4*>(g_n1 + srcR * F + fb);
        float4 c;
        c.x = ea.x * W0.x + ea.y * W1.x + ea.z * W2.x + ea.w * W3.x
            + eb.x * W4.x + eb.y * W5.x + eb.z * W6.x;
        c.y = ea.x * W0.y + ea.y * W1.y + ea.z * W2.y + ea.w * W3.y
            + eb.x * W4.y + eb.y * W5.y + eb.z * W6.y;
        c.z = ea.x * W0.z + ea.y * W1.z + ea.z * W2.z + ea.w * W3.z
            + eb.x * W4.z + eb.y * W5.z + eb.z * W6.z;
        c.w = ea.x * W0.w + ea.y * W1.w + ea.z * W2.w + ea.w * W3.w
            + eb.x * W4.w + eb.y * W5.w + eb.z * W6.w;
        float4 xv;
        xv.x = lrelu(v.x + c.x);
        xv.y = lrelu(v.y + c.y);
        xv.z = lrelu(v.z + c.z);
        xv.w = lrelu(v.w + c.w);
        float part = xv.x * AL.x + xv.y * AL.y + xv.z * AL.z + xv.w * AL.w;
#pragma unroll
        for (int o = 8; o; o >>= 1) part += __shfl_xor_sync(0xffffffffu, part, o);
        float w = __expf(lrelu(part + ri));
        if (g == 0) {
            s += w;
            acc.x = fmaf(w, xv.x, acc.x);
            acc.y = fmaf(w, xv.y, acc.y);
            acc.z = fmaf(w, xv.z, acc.z);
            acc.w = fmaf(w, xv.w, acc.w);
        }
    }
    // ---- combine the two groups, normalize, store ----
    s     += __shfl_xor_sync(0xffffffffu, s, 16);
    acc.x += __shfl_xor_sync(0xffffffffu, acc.x, 16);
    acc.y += __shfl_xor_sync(0xffffffffu, acc.y, 16);
    acc.z += __shfl_xor_sync(0xffffffffu, acc.z, 16);
    acc.w += __shfl_xor_sync(0xffffffffu, acc.w, 16);
    float inv = 1.f / (s + 1e-16f);
    if (g == 0)
        *reinterpret_cast<float4*>(g_t + node * F + fb) =
            make_float4(acc.x * inv, acc.y * inv, acc.z * inv, acc.w * inv);
}

// ---------------- fused: update layer l + prep layer l+1 ----------------
__global__ void k_upprep(const float* __restrict__ w2, const float* __restrict__ b,
                         const float* __restrict__ w1n, const float* __restrict__ arn,
                         int lout) {
    __shared__ float s_w2[F * F];
    __shared__ float s_w1[F * F];
    __shared__ float s_b[F];
    __shared__ float s_ar[F];
    __shared__ float s_x[8][F];
    int tid = threadIdx.x;
    for (int i = tid; i < F * F; i += blockDim.x) { s_w2[i] = w2[i]; s_w1[i] = w1n[i]; }
    if (tid < F) { s_b[tid] = b[tid]; s_ar[tid] = arn[tid]; }
    __syncthreads();
    int warp = tid >> 5, lane = tid & 31;
    int node = blockIdx.x * 8 + warp;
    if (node >= NN) return;
    reinterpret_cast<float2*>(&s_x[warp][0])[lane] =
        reinterpret_cast<const float2*>(g_t + node * F)[lane];
    __syncwarp();
    float2 bb = reinterpret_cast<const float2*>(s_b)[lane];
    float a0 = bb.x, a1 = bb.y;
#pragma unroll 16
    for (int k = 0; k < F; k++) {
        float tv = s_x[warp][k];
        float2 wv = reinterpret_cast<const float2*>(s_w2 + k * F)[lane];
        a0 += tv * wv.x;
        a1 += tv * wv.y;
    }
    float2 h2 = make_float2(fmaxf(a0, 0.f), fmaxf(a1, 0.f));
    reinterpret_cast<float2*>(g_feats[lout] + node * F)[lane] = h2;
    __syncwarp();
    reinterpret_cast<float2*>(&s_x[warp][0])[lane] = h2;
    __syncwarp();
    float n0 = 0.f, n1v = 0.f;
#pragma unroll 16
    for (int k = 0; k < F; k++) {
        float hv = s_x[warp][k];
        float2 wv = reinterpret_cast<const float2*>(s_w1 + k * F)[lane];
        n0 += hv * wv.x;
        n1v += hv * wv.y;
    }
    reinterpret_cast<float2*>(g_n1 + node * F)[lane] = make_float2(n0, n1v);
    float2 ar2 = reinterpret_cast<const float2*>(s_ar)[lane];
    float p = h2.x * ar2.x + h2.y * ar2.y;
#pragma unroll
    for (int o = 16; o; o >>= 1) p += __shfl_xor_sync(0xffffffffu, p, o);
    if (lane == 0) g_r[node] = p;
}

// ---------------- fused: update layer2 + head ----------------
__global__ void k_uphead(const float* __restrict__ w2, const float* __restrict__ b,
                         const float* __restrict__ fc1, const float* __restrict__ b1,
                         const float* __restrict__ fc2, const float* __restrict__ b2,
                         float* __restrict__ out) {
    __shared__ float s_w2[F * F];
    __shared__ float s_b[F];
    __shared__ float s_fc1[256 * 20];
    __shared__ float s_fc2[20];
    __shared__ float s_b1[20];
    __shared__ float s_h[8][256];
    int tid = threadIdx.x;
    for (int i = tid; i < F * F; i += blockDim.x) s_w2[i] = w2[i];
    for (int i = tid; i < 256 * 20; i += blockDim.x) s_fc1[i] = fc1[i];
    if (tid < F) s_b[tid] = b[tid];
    if (tid < 20) { s_fc2[tid] = fc2[tid]; s_b1[tid] = b1[tid]; }
    __syncthreads();
    int warp = tid >> 5, lane = tid & 31;
    int node = blockIdx.x * 8 + warp;
    if (node >= NN) return;
    reinterpret_cast<float2*>(&s_h[warp][192])[lane] =
        reinterpret_cast<const float2*>(g_t + node * F)[lane];
    __syncwarp();
    float2 bb = reinterpret_cast<const float2*>(s_b)[lane];
    float a0 = bb.x, a1 = bb.y;
#pragma unroll 16
    for (int k = 0; k < F; k++) {
        float tv = s_h[warp][192 + k];
        float2 wv = reinterpret_cast<const float2*>(s_w2 + k * F)[lane];
        a0 += tv * wv.x;
        a1 += tv * wv.y;
    }
    __syncwarp();
    reinterpret_cast<float2*>(&s_h[warp][192])[lane] =
        make_float2(fmaxf(a0, 0.f), fmaxf(a1, 0.f));
#pragma unroll
    for (int c = 0; c < 3; c++)
        reinterpret_cast<float2*>(&s_h[warp][c * 64])[lane] =
            reinterpret_cast<const float2*>(g_feats[c] + node * F)[lane];
    __syncwarp();
    float z = 0.f;
    if (lane < 20) {
        float z0 = 0.f, z1 = 0.f, z2 = 0.f, z3 = 0.f;
        for (int f = 0; f < 256; f += 4) {
            z0 += s_h[warp][f]     * s_fc1[f * 20 + lane];
            z1 += s_h[warp][f + 1] * s_fc1[(f + 1) * 20 + lane];
            z2 += s_h[warp][f + 2] * s_fc1[(f + 2) * 20 + lane];
            z3 += s_h[warp][f + 3] * s_fc1[(f + 3) * 20 + lane];
        }
        z = s_b1[lane] + (z0 + z1) + (z2 + z3);
        z = fmaxf(z, 0.f) * s_fc2[lane];
    }
#pragma unroll
    for (int o = 16; o; o >>= 1) z += __shfl_xor_sync(0xffffffffu, z, o);
    if (lane == 0) out[node] = 1.f / (1.f + __expf(-(z + b2[0])));
}

// ---------------- launch ----------------
extern "C" void kernel_launch(void* const* d_in, const int* in_sizes, int n_in,
                              void* d_out, int out_size) {
    const int*   x     = (const int*)  d_in[0];
    const int*   ei    = (const int*)  d_in[1];   // [2, E]
    const float* eattr = (const float*)d_in[2];   // [E, 7]
    const float* emb   = (const float*)d_in[3];   // [VOCAB, 64]
    const float* lin1  = (const float*)d_in[4];   // [3, 71, 64]
    const float* attl  = (const float*)d_in[5];   // [3, 64]
    const float* attr_ = (const float*)d_in[6];   // [3, 64]
    const float* lin2  = (const float*)d_in[7];   // [3, 64, 64]
    const float* gb    = (const float*)d_in[8];   // [3, 64]
    const float* fc1   = (const float*)d_in[9];   // [256, 20]
    const float* fb1   = (const float*)d_in[10];  // [20]
    const float* fc2   = (const float*)d_in[11];  // [20, 1]
    const float* fb2   = (const float*)d_in[12];  // [1]
    float* out = (float*)d_out;

    int nb = (NN + 7) / 8;  // warp per node, 8 warps/block

    k_hist<<<(NE + 255) / 256, 256>>>(ei);
    k_scan_a<<<NSB, SCAN_BS>>>();
    k_scan_b<<<1, 128>>>();
    k_scan_c<<<NSB, SCAN_BS>>>();
    k_scatter<<<(NE + 255) / 256, 256>>>(ei, eattr);
    k_gprep<<<nb, 256>>>(x, emb, lin1, attr_);

    k_edge<<<nb, 256>>>(lin1, attl);
    k_upprep<<<nb, 256>>>(lin2, gb, lin1 + 1 * 71 * F, attr_ + 1 * F, 1);
    k_edge<<<nb, 256>>>(lin1 + 1 * 71 * F, attl + 1 * F);
    k_upprep<<<nb, 256>>>(lin2 + 1 * F * F, gb + 1 * F, lin1 + 2 * 71 * F, attr_ + 2 * F, 2);
    k_edge<<<nb, 256>>>(lin1 + 2 * 71 * F, attl + 2 * F);
    k_uphead<<<nb, 256>>>(lin2 + 2 * F * F, gb + 2 * F, fc1, fb1, fc2, fb2, out);
}